// round 13
// baseline (speedup 1.0000x reference)
#include <cuda_runtime.h>
#include <cuda_fp16.h>

#define BATCH 2
#define C_CH  256
#define FH    192
#define FW    192
#define PH    7
#define PW    7
#define NBIN  (PH*PW)          // 49
#define PLANE (FH*FW)          // 36864
#define SMEM_PITCH 257         // odd pitch -> conflict-free column reads
#define MAXBIN 25              // bins per block (split 25/24)

// NHWC fp16 copy of the feature map: (B, H, W, C) = 37.7 MB
__device__ __half g_nhwc[BATCH * FH * FW * C_CH];

// ---------------------------------------------------------------------------
// Kernel 1 (v2): NCHW fp32 -> NHWC fp16 transpose.
// Tile 64p x 64c per 256-thread block.
//  - load : float2 (p, p+1) for channel pair (c, c+1) -> two half2 in regs
//  - smem : uint tile [64][33]; logical p-rows 2tx -> physical tx,
//           2tx+1 -> physical tx+32. STS.32 banks = tx + const (CF);
//           read banks = (l>>3) + 4*(l&7), bijection on 0..31 (CF).
//  - store: assemble uint4 (8 consecutive channels) -> STG.128 coalesced.
// ---------------------------------------------------------------------------
__global__ __launch_bounds__(256)
void transpose_kernel(const float* __restrict__ in)
{
    __shared__ unsigned int htile[64 * 33];   // 8.4 KB
    int pTile = blockIdx.x * 64;
    int cTile = blockIdx.y * 64;
    int b     = blockIdx.z;
    int tx = threadIdx.x;      // 0..31
    int ty = threadIdx.y;      // 0..7
    int tid = ty * 32 + tx;

    const float* src = in + (size_t)b * C_CH * PLANE;

    #pragma unroll
    for (int i = 0; i < 4; i++) {
        int cpair = ty * 4 + i;              // 0..31 -> channels 2cpair, 2cpair+1
        int c0 = cTile + 2 * cpair;
        const float2* r0 = (const float2*)(src + (size_t)c0 * PLANE + pTile);
        const float2* r1 = (const float2*)(src + (size_t)(c0 + 1) * PLANE + pTile);
        float2 a = __ldg(r0 + tx);           // p = pTile + 2tx, 2tx+1
        float2 d = __ldg(r1 + tx);
        __half2 h0 = __floats2half2_rn(a.x, d.x);   // logical row 2tx
        __half2 h1 = __floats2half2_rn(a.y, d.y);   // logical row 2tx+1
        htile[tx * 33 + cpair]        = *(unsigned int*)&h0;
        htile[(tx + 32) * 33 + cpair] = *(unsigned int*)&h1;
    }
    __syncthreads();

    // 64 rows x 8 quads (uint4 of 4 cpairs = 8 channels) = 512 quads, 2/thread
    #pragma unroll
    for (int k = 0; k < 2; k++) {
        int idx = tid + k * 256;
        int rphys = idx >> 3;                // physical row 0..63
        int q     = idx & 7;                 // quad 0..7
        int p_local = (rphys < 32) ? (2 * rphys) : (2 * (rphys - 32) + 1);

        const unsigned int* rp = &htile[rphys * 33 + 4 * q];
        uint4 v;
        v.x = rp[0]; v.y = rp[1]; v.z = rp[2]; v.w = rp[3];

        size_t p = (size_t)(pTile + p_local);
        *(uint4*)((__half*)g_nhwc + ((size_t)b * PLANE + p) * C_CH
                  + cTile + 8 * q) = v;
    }
}

// ---------------------------------------------------------------------------
// Kernel 2: unchanged from R12 except __launch_bounds__(256, 6) to push
// occupancy 5 -> 6 CTAs/SM (regs 48 -> 42 target).
// ---------------------------------------------------------------------------
__device__ __forceinline__ void load_taps(const uint4* __restrict__ fp,
                                          int4 off, int cg, uint4 q[4])
{
    q[0] = __ldg(fp + off.x + cg);
    q[1] = __ldg(fp + off.y + cg);
    q[2] = __ldg(fp + off.z + cg);
    q[3] = __ldg(fp + off.w + cg);
}

__device__ __forceinline__ void acc_sample(const uint4 q[4], uint4 wq,
                                           float a[8])
{
    __half2 p0 = __float2half2_rn(0.f);
    __half2 p1 = p0, p2 = p0, p3 = p0;

    #pragma unroll
    for (int k = 0; k < 4; k++) {
        unsigned int wu = (k == 0) ? wq.x : (k == 1) ? wq.y
                        : (k == 2) ? wq.z : wq.w;
        __half2 w2 = *(__half2*)&wu;
        const __half2* h = (const __half2*)&q[k];
        p0 = __hfma2(h[0], w2, p0);
        p1 = __hfma2(h[1], w2, p1);
        p2 = __hfma2(h[2], w2, p2);
        p3 = __hfma2(h[3], w2, p3);
    }

    float2 f0 = __half22float2(p0);
    float2 f1 = __half22float2(p1);
    float2 f2 = __half22float2(p2);
    float2 f3 = __half22float2(p3);
    a[0] += f0.x; a[1] += f0.y; a[2] += f1.x; a[3] += f1.y;
    a[4] += f2.x; a[5] += f2.y; a[6] += f3.x; a[7] += f3.y;
}

template<int S0, int CNT>
__device__ __forceinline__
void roi_body(float* sacc, int4* goff, uint4* gwh,
              const float* __restrict__ rois,
              const void*  __restrict__ stride_ptr,
              float* __restrict__ out)
{
    int n   = blockIdx.x;
    int tid = threadIdx.x;
    int cg  = tid & 31;        // channel group: channels 8cg..8cg+7
    int sg  = tid >> 5;        // bin subset 0..7

    const float* r = rois + n * 5;
    int b = (int)r[0];

    // ---- Phase A: geometry precompute (one thread per sample) ----
    if (tid < CNT * 4) {
        int iv = *(const int*)stride_ptr;
        float stride_f = (iv > 0 && iv < 65536) ? (float)iv
                                                : *(const float*)stride_ptr;
        float scale = 1.0f / stride_f;

        float x1 = r[1] * scale;
        float y1 = r[2] * scale;
        float x2 = r[3] * scale;
        float y2 = r[4] * scale;
        float bin_w = fmaxf(x2 - x1, 1.0f) * (1.0f / PW);
        float bin_h = fmaxf(y2 - y1, 1.0f) * (1.0f / PH);

        int s  = S0 + (tid >> 2);
        int j  = tid & 3;
        int iy = j >> 1;
        int ix = j & 1;
        int ph = s / PW;
        int pw = s - ph * PW;

        float yy = y1 + ((float)(ph * 2 + iy) + 0.5f) * 0.5f * bin_h;
        float xx = x1 + ((float)(pw * 2 + ix) + 0.5f) * 0.5f * bin_w;
        bool vy = (yy > -1.0f) && (yy < (float)FH);
        bool vx = (xx > -1.0f) && (xx < (float)FW);

        float cy = fminf(fmaxf(yy, 0.0f), (float)(FH - 1));
        float cx = fminf(fmaxf(xx, 0.0f), (float)(FW - 1));
        int y0 = min((int)floorf(cy), FH - 1);
        int x0 = min((int)floorf(cx), FW - 1);
        int y1r = min(y0 + 1, FH - 1);
        int x1r = min(x0 + 1, FW - 1);
        float fy = cy - (float)y0;
        float fx = cx - (float)x0;
        float hy = 1.0f - fy;
        float hx = 1.0f - fx;

        // fold mask and the 1/4 mean into fp16-duplicated weights
        float m = (vy && vx) ? 0.25f : 0.0f;
        __half2 w00 = __float2half2_rn(m * hy * hx);
        __half2 w01 = __float2half2_rn(m * hy * fx);
        __half2 w10 = __float2half2_rn(m * fy * hx);
        __half2 w11 = __float2half2_rn(m * fy * fx);
        uint4 wq;
        wq.x = *(unsigned int*)&w00;
        wq.y = *(unsigned int*)&w01;
        wq.z = *(unsigned int*)&w10;
        wq.w = *(unsigned int*)&w11;
        gwh[tid]  = wq;
        goff[tid] = make_int4((y0  * FW + x0 ) * (C_CH/8),
                              (y0  * FW + x1r) * (C_CH/8),
                              (y1r * FW + x0 ) * (C_CH/8),
                              (y1r * FW + x1r) * (C_CH/8));
    }
    __syncthreads();

    // ---- Phase B: accumulate, 2-sample pipelined loads (MLP 8) ----
    const uint4* fp = (const uint4*)(g_nhwc) + (size_t)b * PLANE * (C_CH / 8);

    for (int sl = sg; sl < CNT; sl += 8) {
        float a[8] = {0.f, 0.f, 0.f, 0.f, 0.f, 0.f, 0.f, 0.f};

        uint4 qa[4], qb[4];
        load_taps(fp, goff[sl*4+0], cg, qa);   // sample 0 in flight
        load_taps(fp, goff[sl*4+1], cg, qb);   // sample 1 in flight (MLP 8)
        acc_sample(qa, gwh[sl*4+0], a);
        load_taps(fp, goff[sl*4+2], cg, qa);   // sample 2 in flight
        acc_sample(qb, gwh[sl*4+1], a);
        load_taps(fp, goff[sl*4+3], cg, qb);   // sample 3 in flight
        acc_sample(qa, gwh[sl*4+2], a);
        acc_sample(qb, gwh[sl*4+3], a);

        // channel-interleaved store: c = 8*cg + k  ->  word k*32 + cg
        float* sp = &sacc[sl * SMEM_PITCH + cg];
        #pragma unroll
        for (int k = 0; k < 8; k++)
            sp[k * 32] = a[k];                 // STS.32, lanes stride 1: no conflict
    }

    __syncthreads();

    // ---- Phase C: coalesced writeout out[n][c][S0+sl] ----
    // read: word sl*257 + (c&7)*32 + (c>>3); lane stride 257 === 1 mod 32
    float* obase = out + (size_t)n * (C_CH * NBIN) + S0;
    for (int t = tid; t < C_CH * CNT; t += 256) {
        int c  = t / CNT;          // constexpr CNT -> magic multiply
        int sl = t - c * CNT;
        obase[c * NBIN + sl] = sacc[sl * SMEM_PITCH + (c & 7) * 32 + (c >> 3)];
    }
}

__global__ __launch_bounds__(256, 6)
void roi_align_nhwc_kernel(const float* __restrict__ rois,
                           const void*  __restrict__ stride_ptr,
                           float* __restrict__ out)
{
    __shared__ float sacc[MAXBIN * SMEM_PITCH];  // ~25.7 KB
    __shared__ int4  goff[MAXBIN * 4];           // 1.6 KB
    __shared__ uint4 gwh[MAXBIN * 4];            // 1.6 KB

    if (blockIdx.y == 0)
        roi_body<0, 25>(sacc, goff, gwh, rois, stride_ptr, out);
    else
        roi_body<25, 24>(sacc, goff, gwh, rois, stride_ptr, out);
}

extern "C" void kernel_launch(void* const* d_in, const int* in_sizes, int n_in,
                              void* d_out, int out_size)
{
    const float* rois    = (const float*)d_in[0];
    const float* feature = (const float*)d_in[1];
    const void*  stridep = d_in[2];
    float* out = (float*)d_out;

    int N = in_sizes[0] / 5;

    dim3 tgrid(PLANE / 64, C_CH / 64, BATCH);   // 576 x 4 x 2
    dim3 tblk(32, 8);
    transpose_kernel<<<tgrid, tblk>>>(feature);

    dim3 rgrid(N, 2);
    roi_align_nhwc_kernel<<<rgrid, 256>>>(rois, stridep, out);
}

// round 14
// speedup vs baseline: 1.1821x; 1.1821x over previous
#include <cuda_runtime.h>
#include <cuda_fp16.h>

#define BATCH 2
#define C_CH  256
#define FH    192
#define FW    192
#define PH    7
#define PW    7
#define NBIN  (PH*PW)          // 49
#define PLANE (FH*FW)          // 36864
#define SMEM_PITCH 257         // odd pitch -> conflict-free column reads
#define MAXBIN 25              // bins per block (split 25/24)

// NHWC fp16 copy of the feature map: (B, H, W, C) = 37.7 MB
__device__ __half g_nhwc[BATCH * FH * FW * C_CH];

// ---------------------------------------------------------------------------
// Kernel 1 (v2, from R13 — kept): NCHW fp32 -> NHWC fp16 transpose.
// Tile 64p x 64c per 256-thread block; float2 loads, conflict-free smem
// (row-permuted, pitch 33), uint4 STG.128 of 8 consecutive channels.
// ---------------------------------------------------------------------------
__global__ __launch_bounds__(256)
void transpose_kernel(const float* __restrict__ in)
{
    __shared__ unsigned int htile[64 * 33];   // 8.4 KB
    int pTile = blockIdx.x * 64;
    int cTile = blockIdx.y * 64;
    int b     = blockIdx.z;
    int tx = threadIdx.x;      // 0..31
    int ty = threadIdx.y;      // 0..7
    int tid = ty * 32 + tx;

    const float* src = in + (size_t)b * C_CH * PLANE;

    #pragma unroll
    for (int i = 0; i < 4; i++) {
        int cpair = ty * 4 + i;              // 0..31 -> channels 2cpair, 2cpair+1
        int c0 = cTile + 2 * cpair;
        const float2* r0 = (const float2*)(src + (size_t)c0 * PLANE + pTile);
        const float2* r1 = (const float2*)(src + (size_t)(c0 + 1) * PLANE + pTile);
        float2 a = __ldg(r0 + tx);           // p = pTile + 2tx, 2tx+1
        float2 d = __ldg(r1 + tx);
        __half2 h0 = __floats2half2_rn(a.x, d.x);   // logical row 2tx
        __half2 h1 = __floats2half2_rn(a.y, d.y);   // logical row 2tx+1
        htile[tx * 33 + cpair]        = *(unsigned int*)&h0;
        htile[(tx + 32) * 33 + cpair] = *(unsigned int*)&h1;
    }
    __syncthreads();

    // 64 rows x 8 quads (uint4 of 4 cpairs = 8 channels) = 512 quads, 2/thread
    #pragma unroll
    for (int k = 0; k < 2; k++) {
        int idx = tid + k * 256;
        int rphys = idx >> 3;                // physical row 0..63
        int q     = idx & 7;                 // quad 0..7
        int p_local = (rphys < 32) ? (2 * rphys) : (2 * (rphys - 32) + 1);

        const unsigned int* rp = &htile[rphys * 33 + 4 * q];
        uint4 v;
        v.x = rp[0]; v.y = rp[1]; v.z = rp[2]; v.w = rp[3];

        size_t p = (size_t)(pTile + p_local);
        *(uint4*)((__half*)g_nhwc + ((size_t)b * PLANE + p) * C_CH
                  + cTile + 8 * q) = v;
    }
}

// ---------------------------------------------------------------------------
// Kernel 2 (exactly R12, the 35.1us configuration): one block = CNT bins of
// one roi; cg = tid&31 -> 8 fp16 ch via uint4 LDG.128; 2-sample pipelined
// loads (MLP 8); HFMA2 partials + fp32 accumulate; channel-interleaved
// conflict-free staging; __launch_bounds__(256, 5) -> regs=48, 5 CTAs/SM.
// ---------------------------------------------------------------------------
__device__ __forceinline__ void load_taps(const uint4* __restrict__ fp,
                                          int4 off, int cg, uint4 q[4])
{
    q[0] = __ldg(fp + off.x + cg);
    q[1] = __ldg(fp + off.y + cg);
    q[2] = __ldg(fp + off.z + cg);
    q[3] = __ldg(fp + off.w + cg);
}

__device__ __forceinline__ void acc_sample(const uint4 q[4], uint4 wq,
                                           float a[8])
{
    __half2 p0 = __float2half2_rn(0.f);
    __half2 p1 = p0, p2 = p0, p3 = p0;

    #pragma unroll
    for (int k = 0; k < 4; k++) {
        unsigned int wu = (k == 0) ? wq.x : (k == 1) ? wq.y
                        : (k == 2) ? wq.z : wq.w;
        __half2 w2 = *(__half2*)&wu;
        const __half2* h = (const __half2*)&q[k];
        p0 = __hfma2(h[0], w2, p0);
        p1 = __hfma2(h[1], w2, p1);
        p2 = __hfma2(h[2], w2, p2);
        p3 = __hfma2(h[3], w2, p3);
    }

    float2 f0 = __half22float2(p0);
    float2 f1 = __half22float2(p1);
    float2 f2 = __half22float2(p2);
    float2 f3 = __half22float2(p3);
    a[0] += f0.x; a[1] += f0.y; a[2] += f1.x; a[3] += f1.y;
    a[4] += f2.x; a[5] += f2.y; a[6] += f3.x; a[7] += f3.y;
}

template<int S0, int CNT>
__device__ __forceinline__
void roi_body(float* sacc, int4* goff, uint4* gwh,
              const float* __restrict__ rois,
              const void*  __restrict__ stride_ptr,
              float* __restrict__ out)
{
    int n   = blockIdx.x;
    int tid = threadIdx.x;
    int cg  = tid & 31;        // channel group: channels 8cg..8cg+7
    int sg  = tid >> 5;        // bin subset 0..7

    const float* r = rois + n * 5;
    int b = (int)r[0];

    // ---- Phase A: geometry precompute (one thread per sample) ----
    if (tid < CNT * 4) {
        int iv = *(const int*)stride_ptr;
        float stride_f = (iv > 0 && iv < 65536) ? (float)iv
                                                : *(const float*)stride_ptr;
        float scale = 1.0f / stride_f;

        float x1 = r[1] * scale;
        float y1 = r[2] * scale;
        float x2 = r[3] * scale;
        float y2 = r[4] * scale;
        float bin_w = fmaxf(x2 - x1, 1.0f) * (1.0f / PW);
        float bin_h = fmaxf(y2 - y1, 1.0f) * (1.0f / PH);

        int s  = S0 + (tid >> 2);
        int j  = tid & 3;
        int iy = j >> 1;
        int ix = j & 1;
        int ph = s / PW;
        int pw = s - ph * PW;

        float yy = y1 + ((float)(ph * 2 + iy) + 0.5f) * 0.5f * bin_h;
        float xx = x1 + ((float)(pw * 2 + ix) + 0.5f) * 0.5f * bin_w;
        bool vy = (yy > -1.0f) && (yy < (float)FH);
        bool vx = (xx > -1.0f) && (xx < (float)FW);

        float cy = fminf(fmaxf(yy, 0.0f), (float)(FH - 1));
        float cx = fminf(fmaxf(xx, 0.0f), (float)(FW - 1));
        int y0 = min((int)floorf(cy), FH - 1);
        int x0 = min((int)floorf(cx), FW - 1);
        int y1r = min(y0 + 1, FH - 1);
        int x1r = min(x0 + 1, FW - 1);
        float fy = cy - (float)y0;
        float fx = cx - (float)x0;
        float hy = 1.0f - fy;
        float hx = 1.0f - fx;

        // fold mask and the 1/4 mean into fp16-duplicated weights
        float m = (vy && vx) ? 0.25f : 0.0f;
        __half2 w00 = __float2half2_rn(m * hy * hx);
        __half2 w01 = __float2half2_rn(m * hy * fx);
        __half2 w10 = __float2half2_rn(m * fy * hx);
        __half2 w11 = __float2half2_rn(m * fy * fx);
        uint4 wq;
        wq.x = *(unsigned int*)&w00;
        wq.y = *(unsigned int*)&w01;
        wq.z = *(unsigned int*)&w10;
        wq.w = *(unsigned int*)&w11;
        gwh[tid]  = wq;
        goff[tid] = make_int4((y0  * FW + x0 ) * (C_CH/8),
                              (y0  * FW + x1r) * (C_CH/8),
                              (y1r * FW + x0 ) * (C_CH/8),
                              (y1r * FW + x1r) * (C_CH/8));
    }
    __syncthreads();

    // ---- Phase B: accumulate, 2-sample pipelined loads (MLP 8) ----
    const uint4* fp = (const uint4*)(g_nhwc) + (size_t)b * PLANE * (C_CH / 8);

    for (int sl = sg; sl < CNT; sl += 8) {
        float a[8] = {0.f, 0.f, 0.f, 0.f, 0.f, 0.f, 0.f, 0.f};

        uint4 qa[4], qb[4];
        load_taps(fp, goff[sl*4+0], cg, qa);   // sample 0 in flight
        load_taps(fp, goff[sl*4+1], cg, qb);   // sample 1 in flight (MLP 8)
        acc_sample(qa, gwh[sl*4+0], a);
        load_taps(fp, goff[sl*4+2], cg, qa);   // sample 2 in flight
        acc_sample(qb, gwh[sl*4+1], a);
        load_taps(fp, goff[sl*4+3], cg, qb);   // sample 3 in flight
        acc_sample(qa, gwh[sl*4+2], a);
        acc_sample(qb, gwh[sl*4+3], a);

        // channel-interleaved store: c = 8*cg + k  ->  word k*32 + cg
        float* sp = &sacc[sl * SMEM_PITCH + cg];
        #pragma unroll
        for (int k = 0; k < 8; k++)
            sp[k * 32] = a[k];                 // STS.32, lanes stride 1: no conflict
    }

    __syncthreads();

    // ---- Phase C: coalesced writeout out[n][c][S0+sl] ----
    // read: word sl*257 + (c&7)*32 + (c>>3); lane stride 257 === 1 mod 32
    float* obase = out + (size_t)n * (C_CH * NBIN) + S0;
    for (int t = tid; t < C_CH * CNT; t += 256) {
        int c  = t / CNT;          // constexpr CNT -> magic multiply
        int sl = t - c * CNT;
        obase[c * NBIN + sl] = sacc[sl * SMEM_PITCH + (c & 7) * 32 + (c >> 3)];
    }
}

__global__ __launch_bounds__(256, 5)
void roi_align_nhwc_kernel(const float* __restrict__ rois,
                           const void*  __restrict__ stride_ptr,
                           float* __restrict__ out)
{
    __shared__ float sacc[MAXBIN * SMEM_PITCH];  // ~25.7 KB
    __shared__ int4  goff[MAXBIN * 4];           // 1.6 KB
    __shared__ uint4 gwh[MAXBIN * 4];            // 1.6 KB

    if (blockIdx.y == 0)
        roi_body<0, 25>(sacc, goff, gwh, rois, stride_ptr, out);
    else
        roi_body<25, 24>(sacc, goff, gwh, rois, stride_ptr, out);
}

extern "C" void kernel_launch(void* const* d_in, const int* in_sizes, int n_in,
                              void* d_out, int out_size)
{
    const float* rois    = (const float*)d_in[0];
    const float* feature = (const float*)d_in[1];
    const void*  stridep = d_in[2];
    float* out = (float*)d_out;

    int N = in_sizes[0] / 5;

    dim3 tgrid(PLANE / 64, C_CH / 64, BATCH);   // 576 x 4 x 2
    dim3 tblk(32, 8);
    transpose_kernel<<<tgrid, tblk>>>(feature);

    dim3 rgrid(N, 2);
    roi_align_nhwc_kernel<<<rgrid, 256>>>(rois, stridep, out);
}